// round 10
// baseline (speedup 1.0000x reference)
#include <cuda_runtime.h>
#include <cuda_bf16.h>

#define NT     2000
#define NS     2048
#define NH     16
#define CHUNK  16            // steps per chunk; NT = 125*16
#define NCHUNK (NT / CHUNK)  // 125
#define SPB    16            // sites per block
#define THREADS 256          // SPB * NH
#define WARPS   8
#define QPAD    36           // padded row stride for qsm (16B-aligned, low conflicts)

__device__ __forceinline__ float sigmoidf_(float x) {
    return 1.0f / (1.0f + expf(-x));
}

__global__ __launch_bounds__(THREADS, 1)
void waternet_kernel(const float* __restrict__ P, const float* __restrict__ T,
                     const float* __restrict__ E,
                     const float* __restrict__ w_o, const float* __restrict__ wF,
                     const float* __restrict__ wG, const float* __restrict__ wl,
                     const float* __restrict__ we, const float* __restrict__ wk,
                     const float* __restrict__ ws,
                     float* __restrict__ Qo, float* __restrict__ Fo,
                     float* __restrict__ Ho, float* __restrict__ Go)
{
    __shared__ __align__(16) float tile[2][3][CHUNK][SPB];  // forcings, double-buffered
    __shared__ __align__(16) float qsm[WARPS][CHUNK][QPAD]; // per-warp Q staging

    const unsigned tid  = threadIdx.x;
    const unsigned warp = tid >> 5;
    const unsigned lane = tid & 31;
    const unsigned sl   = tid >> 4;          // local site 0..15
    const unsigned h    = tid & 15;          // head
    const unsigned s0   = blockIdx.x * SPB;  // block's first site
    const unsigned s    = s0 + sl;

    // tile-loader role: thread u loads step (u>>4), local site (u&15)
    const unsigned ljj = tid >> 4;
    const unsigned lss = tid & 15;
    const unsigned lbase0 = ljj * NS + s0 + lss;

    // ---- per-head constants ----
    float ssum = 0.0f;
    #pragma unroll
    for (int i = 0; i < NH; i++) ssum += expf(w_o[i]);
    const float a    = expf(w_o[h]) / ssum;
    const float melt = expf(wF[h]) + 1.0f;
    const float cap  = expf(2.0f * wl[h]);
    const float swe  = sigmoidf_(we[h]);
    const float swk  = sigmoidf_(wk[h]);
    const float sws  = sigmoidf_(ws[h]);
    const float swg  = sigmoidf_(wG[h]);

    float f = 0.0f, hs = 0.0f, g = 0.0f;

    // load chunk 0 into buffer 0
    tile[0][0][ljj][lss] = __ldg(P + lbase0);
    tile[0][1][ljj][lss] = __ldg(T + lbase0);
    tile[0][2][ljj][lss] = __ldg(E + lbase0);
    __syncthreads();

    unsigned oidx = s * NH + h;
    const unsigned out_stride = NS * NH;

    for (int c = 0; c < NCHUNK; c++) {
        const int rd = c & 1;

        // prefetch next chunk into registers (covered by this chunk's compute)
        float rp = 0.0f, rt = 0.0f, re = 0.0f;
        if (c < NCHUNK - 1) {
            const unsigned base = (unsigned)(c + 1) * CHUNK * NS + lbase0;
            rp = __ldg(P + base);
            rt = __ldg(T + base);
            re = __ldg(E + base);
        }

        #pragma unroll
        for (int j = 0; j < CHUNK; j++) {
            const float Pk = tile[rd][0][j][sl];
            const float Tk = tile[rd][1][j][sl];
            const float Ek = tile[rd][2][j][sl];

            // SnowBucket
            const float sm    = fmaxf(Tk, 0.0f) * melt;
            const float pcold = (Tk < 0.0f) ? Pk : 0.0f;
            const float pwarm = (Tk > 0.0f) ? Pk : 0.0f;
            const float m     = fminf(sm, f);
            f = (f - m) + pcold;
            const float x = pwarm + m;

            // SoilBucket (h2 = hn - relu(hn-cap) == min(hn, cap))
            const float hn = hs + x;
            const float h1 = fmaxf(hn - cap, 0.0f);
            const float q1 = fmaxf(h1 - Ek * swe, 0.0f);
            const float h2 = fminf(hn, cap);
            const float q2 = h2 * swk;
            hs = h2 - q2;
            const float q2a = q2 * sws;
            const float q2b = q2 - q2a;

            // LinearBucket
            const float gn = g + q2b;
            const float q3 = gn * swg;
            g = gn - q3;

            // coalesced streaming state stores (128B per warp per array)
            __stcs(Fo + oidx, f);
            __stcs(Ho + oidx, hs);
            __stcs(Go + oidx, g);
            oidx += out_stride;

            // stage this head's Q contribution (reduced once per chunk)
            qsm[warp][j][lane] = (q1 + q2a + q3) * a;
        }

        __syncwarp();
        // per-warp Q reduction: lane -> (local site d, step j); sums 16 heads
        {
            const unsigned d = lane >> 4;
            const unsigned j = lane & 15;
            const float4* q4 = (const float4*)&qsm[warp][j][d * 16];
            const float4 v0 = q4[0], v1 = q4[1], v2 = q4[2], v3 = q4[3];
            const float sum = (((v0.x + v0.y) + (v0.z + v0.w)) +
                               ((v1.x + v1.y) + (v1.z + v1.w))) +
                              (((v2.x + v2.y) + (v2.z + v2.w)) +
                               ((v3.x + v3.y) + (v3.z + v3.w)));
            const unsigned qi = (unsigned)(c * CHUNK + j) * NS + s0 + warp * 2 + d;
            __stcs(Qo + qi, sum);
        }
        __syncwarp();

        // publish prefetched chunk into the other buffer
        if (c < NCHUNK - 1) {
            tile[rd ^ 1][0][ljj][lss] = rp;
            tile[rd ^ 1][1][ljj][lss] = rt;
            tile[rd ^ 1][2][ljj][lss] = re;
        }
        __syncthreads();
    }
}

extern "C" void kernel_launch(void* const* d_in, const int* in_sizes, int n_in,
                              void* d_out, int out_size) {
    const float* big[3]    = {nullptr, nullptr, nullptr};
    const float* small7[7] = {nullptr, nullptr, nullptr, nullptr, nullptr, nullptr, nullptr};
    int nb = 0, nsml = 0;
    for (int i = 0; i < n_in; i++) {
        if (d_in[i] == nullptr) continue;
        if (in_sizes[i] > 10000) {
            if (nb < 3) big[nb++] = (const float*)d_in[i];
        } else if (in_sizes[i] > 0) {
            if (nsml < 7) small7[nsml++] = (const float*)d_in[i];
        }
    }
    if (nb < 3 || nsml < 7) return;

    const float* P   = big[0];
    const float* T   = big[1];
    const float* E   = big[2];
    const float* w_o = small7[0];
    const float* wF  = small7[1];
    const float* wG  = small7[2];
    const float* wl  = small7[3];
    const float* we  = small7[4];
    const float* wk  = small7[5];
    const float* ws  = small7[6];

    float* out = (float*)d_out;
    const long long QN = (long long)NT * NS;
    float* Qo = out;
    float* Fo = Qo + QN;
    float* Ho = Fo + QN * NH;
    float* Go = Ho + QN * NH;

    // 128 blocks x 256 threads = 32768 threads exactly; 8 warps/SM (2 per SMSP).
    const int blocks = NS / SPB;  // 128
    waternet_kernel<<<blocks, THREADS>>>(P, T, E, w_o, wF, wG, wl, we, wk, ws,
                                         Qo, Fo, Ho, Go);
}

// round 14
// speedup vs baseline: 1.0800x; 1.0800x over previous
#include <cuda_runtime.h>
#include <cuda_bf16.h>

#define NT      2000
#define NS      2048
#define NH      16
#define CHUNK   16            // steps per chunk; NT = 125*16
#define NCHUNK  (NT / CHUNK)  // 125
#define SPB     16            // sites per block
#define THREADS 256           // SPB * NH
#define WARPS   8
#define TSTRIDE 20            // tile row stride (floats): 80B, 16B-aligned, low conflicts
#define QPAD    36            // qsm row stride (floats): 144B, 16B-aligned

__device__ __forceinline__ float sigmoidf_(float x) {
    return 1.0f / (1.0f + expf(-x));
}

__global__ __launch_bounds__(THREADS, 1)
void waternet_kernel(const float* __restrict__ P, const float* __restrict__ T,
                     const float* __restrict__ E,
                     const float* __restrict__ w_o, const float* __restrict__ wF,
                     const float* __restrict__ wG, const float* __restrict__ wl,
                     const float* __restrict__ we, const float* __restrict__ wk,
                     const float* __restrict__ ws,
                     float* __restrict__ Qo, float* __restrict__ Fo,
                     float* __restrict__ Ho, float* __restrict__ Go)
{
    // time-major forcing tile: [buf][array][site][step]; read with LDS.128
    __shared__ __align__(16) float tile[2][3][SPB][TSTRIDE];
    __shared__ __align__(16) float qsm[WARPS][CHUNK][QPAD];

    const unsigned tid  = threadIdx.x;
    const unsigned warp = tid >> 5;
    const unsigned lane = tid & 31;
    const unsigned sl   = tid >> 4;          // local site 0..15
    const unsigned h    = tid & 15;          // head
    const unsigned s0   = blockIdx.x * SPB;
    const unsigned s    = s0 + sl;

    // loader role: lane-fast over sites for coalesced LDG
    const unsigned lstep = tid >> 4;         // step 0..15
    const unsigned lsite = tid & 15;         // site 0..15
    const unsigned lbase0 = lstep * NS + s0 + lsite;

    // ---- per-head constants ----
    float ssum = 0.0f;
    #pragma unroll
    for (int i = 0; i < NH; i++) ssum += expf(w_o[i]);
    const float a    = expf(w_o[h]) / ssum;
    const float melt = expf(wF[h]) + 1.0f;
    const float cap  = expf(2.0f * wl[h]);
    const float swe  = sigmoidf_(we[h]);
    const float swk  = sigmoidf_(wk[h]);
    const float sws  = sigmoidf_(ws[h]);
    const float swg  = sigmoidf_(wG[h]);

    float f = 0.0f, hs = 0.0f, g = 0.0f;

    // load chunk 0 into buffer 0 (time-major)
    tile[0][0][lsite][lstep] = __ldg(P + lbase0);
    tile[0][1][lsite][lstep] = __ldg(T + lbase0);
    tile[0][2][lsite][lstep] = __ldg(E + lbase0);
    __syncthreads();

    unsigned oidx = s * NH + h;
    const unsigned out_stride = NS * NH;

    for (int c = 0; c < NCHUNK; c++) {
        const int rd = c & 1;

        // bulk-read this chunk's forcings: 12 x LDS.128 -> registers
        float pv[CHUNK], tv[CHUNK], ev[CHUNK];
        {
            const float4* tp = (const float4*)&tile[rd][0][sl][0];
            const float4* tt = (const float4*)&tile[rd][1][sl][0];
            const float4* te = (const float4*)&tile[rd][2][sl][0];
            #pragma unroll
            for (int q = 0; q < 4; q++) {
                float4 v;
                v = tp[q]; pv[4*q]=v.x; pv[4*q+1]=v.y; pv[4*q+2]=v.z; pv[4*q+3]=v.w;
                v = tt[q]; tv[4*q]=v.x; tv[4*q+1]=v.y; tv[4*q+2]=v.z; tv[4*q+3]=v.w;
                v = te[q]; ev[4*q]=v.x; ev[4*q+1]=v.y; ev[4*q+2]=v.z; ev[4*q+3]=v.w;
            }
        }

        // prefetch next chunk into registers
        float rp = 0.0f, rt = 0.0f, re = 0.0f;
        if (c < NCHUNK - 1) {
            const unsigned base = (unsigned)(c + 1) * CHUNK * NS + lbase0;
            rp = __ldg(P + base);
            rt = __ldg(T + base);
            re = __ldg(E + base);
        }

        #pragma unroll
        for (int j = 0; j < CHUNK; j++) {
            const float Pk = pv[j], Tk = tv[j], Ek = ev[j];

            // SnowBucket
            const float sm    = fmaxf(Tk, 0.0f) * melt;
            const float pcold = (Tk < 0.0f) ? Pk : 0.0f;
            const float pwarm = (Tk > 0.0f) ? Pk : 0.0f;
            const float m     = fminf(sm, f);
            f = (f - m) + pcold;
            const float x = pwarm + m;

            // SoilBucket (h2 = hn - relu(hn-cap) == min(hn, cap))
            const float hn = hs + x;
            const float h1 = fmaxf(hn - cap, 0.0f);
            const float q1 = fmaxf(h1 - Ek * swe, 0.0f);
            const float h2 = fminf(hn, cap);
            const float q2 = h2 * swk;
            hs = h2 - q2;
            const float q2a = q2 * sws;
            const float q2b = q2 - q2a;

            // LinearBucket
            const float gn = g + q2b;
            const float q3 = gn * swg;
            g = gn - q3;

            // coalesced streaming state stores (128B per warp per array)
            __stcs(Fo + oidx, f);
            __stcs(Ho + oidx, hs);
            __stcs(Go + oidx, g);
            oidx += out_stride;

            qsm[warp][j][lane] = (q1 + q2a + q3) * a;
        }

        // publish prefetched chunk (tile[rd^1] was last read in chunk c-1,
        // ordered by that chunk's closing __syncthreads)
        if (c < NCHUNK - 1) {
            tile[rd ^ 1][0][lsite][lstep] = rp;
            tile[rd ^ 1][1][lsite][lstep] = rt;
            tile[rd ^ 1][2][lsite][lstep] = re;
        }

        __syncwarp();
        // per-warp Q reduction: lane -> (local site d, step j); sums 16 heads
        {
            const unsigned d = lane >> 4;
            const unsigned j = lane & 15;
            const float4* q4 = (const float4*)&qsm[warp][j][d * 16];
            const float4 v0 = q4[0], v1 = q4[1], v2 = q4[2], v3 = q4[3];
            const float sum = (((v0.x + v0.y) + (v0.z + v0.w)) +
                               ((v1.x + v1.y) + (v1.z + v1.w))) +
                              (((v2.x + v2.y) + (v2.z + v2.w)) +
                               ((v3.x + v3.y) + (v3.z + v3.w)));
            const unsigned qi = (unsigned)(c * CHUNK + j) * NS + s0 + warp * 2 + d;
            Qo[qi] = sum;   // default policy: let L2 merge partial sectors
        }
        __syncthreads();
    }
}

extern "C" void kernel_launch(void* const* d_in, const int* in_sizes, int n_in,
                              void* d_out, int out_size) {
    const float* big[3]    = {nullptr, nullptr, nullptr};
    const float* small7[7] = {nullptr, nullptr, nullptr, nullptr, nullptr, nullptr, nullptr};
    int nb = 0, nsml = 0;
    for (int i = 0; i < n_in; i++) {
        if (d_in[i] == nullptr) continue;
        if (in_sizes[i] > 10000) {
            if (nb < 3) big[nb++] = (const float*)d_in[i];
        } else if (in_sizes[i] > 0) {
            if (nsml < 7) small7[nsml++] = (const float*)d_in[i];
        }
    }
    if (nb < 3 || nsml < 7) return;

    const float* P   = big[0];
    const float* T   = big[1];
    const float* E   = big[2];
    const float* w_o = small7[0];
    const float* wF  = small7[1];
    const float* wG  = small7[2];
    const float* wl  = small7[3];
    const float* we  = small7[4];
    const float* wk  = small7[5];
    const float* ws  = small7[6];

    float* out = (float*)d_out;
    const long long QN = (long long)NT * NS;
    float* Qo = out;
    float* Fo = Qo + QN;
    float* Ho = Fo + QN * NH;
    float* Go = Ho + QN * NH;

    const int blocks = NS / SPB;  // 128 blocks x 256 threads = 8 warps/SM
    waternet_kernel<<<blocks, THREADS>>>(P, T, E, w_o, wF, wG, wl, we, wk, ws,
                                         Qo, Fo, Ho, Go);
}

// round 15
// speedup vs baseline: 1.1634x; 1.0772x over previous
#include <cuda_runtime.h>
#include <cuda_bf16.h>

#define NT      2000
#define NS      2048
#define NH      16
#define CHUNK   16            // steps per chunk; NT = 125*16
#define NCHUNK  (NT / CHUNK)  // 125
#define SPB     14            // max sites per block
#define THREADS 224           // SPB * NH = 7 warps
#define WARPS   7
#define NBLOCKS 147           // 146*14 + 4 = 2048 sites
#define TSTRIDE 20            // tile row stride (floats): 80B, 16B-aligned
#define QPAD    36            // qsm row stride (floats)

__device__ __forceinline__ float sigmoidf_(float x) {
    return 1.0f / (1.0f + expf(-x));
}

__global__ __launch_bounds__(THREADS, 1)
void waternet_kernel(const float* __restrict__ P, const float* __restrict__ T,
                     const float* __restrict__ E,
                     const float* __restrict__ w_o, const float* __restrict__ wF,
                     const float* __restrict__ wG, const float* __restrict__ wl,
                     const float* __restrict__ we, const float* __restrict__ wk,
                     const float* __restrict__ ws,
                     float* __restrict__ Qo, float* __restrict__ Fo,
                     float* __restrict__ Ho, float* __restrict__ Go)
{
    // time-major forcing tile: [buf][array][site][step]; read with LDS.128
    __shared__ __align__(16) float tile[2][3][SPB][TSTRIDE];
    __shared__ __align__(16) float qsm[WARPS][CHUNK][QPAD];

    const unsigned tid  = threadIdx.x;
    const unsigned warp = tid >> 5;
    const unsigned lane = tid & 31;
    const unsigned sl   = tid >> 4;          // local site 0..13
    const unsigned h    = tid & 15;          // head
    const unsigned s0   = blockIdx.x * SPB;
    const unsigned spb  = (s0 + SPB <= NS) ? SPB : (NS - s0);   // 14, or 4 in last block
    const unsigned s    = s0 + sl;

    const bool comp_on = (sl < spb);         // this thread computes/stores
    // loader role: 224 = 16 steps x 14 sites
    const unsigned lstep = tid / SPB;        // 0..15
    const unsigned lsite = tid % SPB;        // 0..13
    const bool load_on = (lsite < spb);
    const unsigned lbase0 = lstep * NS + s0 + lsite;
    // Q-reduction role: warp covers sites 2w, 2w+1
    const bool qwarp_on = (2 * warp < spb);

    // ---- per-head constants ----
    float ssum = 0.0f;
    #pragma unroll
    for (int i = 0; i < NH; i++) ssum += expf(w_o[i]);
    const float a    = expf(w_o[h]) / ssum;
    const float melt = expf(wF[h]) + 1.0f;
    const float cap  = expf(2.0f * wl[h]);
    const float swe  = sigmoidf_(we[h]);
    const float swk  = sigmoidf_(wk[h]);
    const float sws  = sigmoidf_(ws[h]);
    const float swg  = sigmoidf_(wG[h]);

    float f = 0.0f, hs = 0.0f, g = 0.0f;

    // load chunk 0 into buffer 0 (time-major)
    if (load_on) {
        tile[0][0][lsite][lstep] = __ldg(P + lbase0);
        tile[0][1][lsite][lstep] = __ldg(T + lbase0);
        tile[0][2][lsite][lstep] = __ldg(E + lbase0);
    }
    __syncthreads();

    unsigned oidx = s * NH + h;
    const unsigned out_stride = NS * NH;

    for (int c = 0; c < NCHUNK; c++) {
        const int rd = c & 1;

        // bulk-read this chunk's forcings: 12 x LDS.128 -> registers
        float pv[CHUNK], tv[CHUNK], ev[CHUNK];
        {
            const unsigned slc = comp_on ? sl : 0;   // keep reads in-bounds
            const float4* tp = (const float4*)&tile[rd][0][slc][0];
            const float4* tt = (const float4*)&tile[rd][1][slc][0];
            const float4* te = (const float4*)&tile[rd][2][slc][0];
            #pragma unroll
            for (int q = 0; q < 4; q++) {
                float4 v;
                v = tp[q]; pv[4*q]=v.x; pv[4*q+1]=v.y; pv[4*q+2]=v.z; pv[4*q+3]=v.w;
                v = tt[q]; tv[4*q]=v.x; tv[4*q+1]=v.y; tv[4*q+2]=v.z; tv[4*q+3]=v.w;
                v = te[q]; ev[4*q]=v.x; ev[4*q+1]=v.y; ev[4*q+2]=v.z; ev[4*q+3]=v.w;
            }
        }

        // prefetch next chunk into registers
        float rp = 0.0f, rt = 0.0f, re = 0.0f;
        if (c < NCHUNK - 1 && load_on) {
            const unsigned base = (unsigned)(c + 1) * CHUNK * NS + lbase0;
            rp = __ldg(P + base);
            rt = __ldg(T + base);
            re = __ldg(E + base);
        }

        #pragma unroll
        for (int j = 0; j < CHUNK; j++) {
            const float Pk = pv[j], Tk = tv[j], Ek = ev[j];

            // SnowBucket
            const float sm    = fmaxf(Tk, 0.0f) * melt;
            const float pcold = (Tk < 0.0f) ? Pk : 0.0f;
            const float pwarm = (Tk > 0.0f) ? Pk : 0.0f;
            const float m     = fminf(sm, f);
            f = (f - m) + pcold;
            const float x = pwarm + m;

            // SoilBucket (h2 = hn - relu(hn-cap) == min(hn, cap))
            const float hn = hs + x;
            const float h1 = fmaxf(hn - cap, 0.0f);
            const float q1 = fmaxf(h1 - Ek * swe, 0.0f);
            const float h2 = fminf(hn, cap);
            const float q2 = h2 * swk;
            hs = h2 - q2;
            const float q2a = q2 * sws;
            const float q2b = q2 - q2a;

            // LinearBucket
            const float gn = g + q2b;
            const float q3 = gn * swg;
            g = gn - q3;

            // coalesced streaming state stores
            if (comp_on) {
                __stcs(Fo + oidx, f);
                __stcs(Ho + oidx, hs);
                __stcs(Go + oidx, g);
                qsm[warp][j][lane] = (q1 + q2a + q3) * a;
            }
            oidx += out_stride;
        }

        // publish prefetched chunk (tile[rd^1] last read in chunk c-1,
        // ordered by that chunk's closing __syncthreads)
        if (c < NCHUNK - 1 && load_on) {
            tile[rd ^ 1][0][lsite][lstep] = rp;
            tile[rd ^ 1][1][lsite][lstep] = rt;
            tile[rd ^ 1][2][lsite][lstep] = re;
        }

        __syncwarp();
        // per-warp Q reduction: lane -> (local site d, step j); sums 16 heads
        if (qwarp_on) {
            const unsigned d = lane >> 4;
            const unsigned j = lane & 15;
            const float4* q4 = (const float4*)&qsm[warp][j][d * 16];
            const float4 v0 = q4[0], v1 = q4[1], v2 = q4[2], v3 = q4[3];
            const float sum = (((v0.x + v0.y) + (v0.z + v0.w)) +
                               ((v1.x + v1.y) + (v1.z + v1.w))) +
                              (((v2.x + v2.y) + (v2.z + v2.w)) +
                               ((v3.x + v3.y) + (v3.z + v3.w)));
            const unsigned qi = (unsigned)(c * CHUNK + j) * NS + s0 + warp * 2 + d;
            Qo[qi] = sum;
        }
        __syncthreads();
    }
}

extern "C" void kernel_launch(void* const* d_in, const int* in_sizes, int n_in,
                              void* d_out, int out_size) {
    const float* big[3]    = {nullptr, nullptr, nullptr};
    const float* small7[7] = {nullptr, nullptr, nullptr, nullptr, nullptr, nullptr, nullptr};
    int nb = 0, nsml = 0;
    for (int i = 0; i < n_in; i++) {
        if (d_in[i] == nullptr) continue;
        if (in_sizes[i] > 10000) {
            if (nb < 3) big[nb++] = (const float*)d_in[i];
        } else if (in_sizes[i] > 0) {
            if (nsml < 7) small7[nsml++] = (const float*)d_in[i];
        }
    }
    if (nb < 3 || nsml < 7) return;

    const float* P   = big[0];
    const float* T   = big[1];
    const float* E   = big[2];
    const float* w_o = small7[0];
    const float* wF  = small7[1];
    const float* wG  = small7[2];
    const float* wl  = small7[3];
    const float* we  = small7[4];
    const float* wk  = small7[5];
    const float* ws  = small7[6];

    float* out = (float*)d_out;
    const long long QN = (long long)NT * NS;
    float* Qo = out;
    float* Fo = Qo + QN;
    float* Ho = Fo + QN * NH;
    float* Go = Ho + QN * NH;

    // 147 blocks x 224 threads: 146 blocks of 14 sites + 1 block of 4 sites.
    // One block per SM on 147 of 148 SMs; 7 warps/SM.
    waternet_kernel<<<NBLOCKS, THREADS>>>(P, T, E, w_o, wF, wG, wl, we, wk, ws,
                                          Qo, Fo, Ho, Go);
}